// round 3
// baseline (speedup 1.0000x reference)
#include <cuda_runtime.h>
#include <math.h>

// Problem constants (fixed by the dataset)
#define SLEN 2048          // src_len
#define TLEN 1024          // tgt_len
#define NB   32            // batch
#define HID  1024          // hidden
#define LDA  (NB * HID)    // stride between time steps in [time, B, H] tensors

#define TILE 128
#define KT   16

// ctx scratch: [T, B, H] laid out as m*HID + h with m = t*NB + b  (matches dec layout)
__device__ float g_ctx[(size_t)TLEN * NB * HID];

// ---------------------------------------------------------------------------
// Shared-memory tile loaders
// ---------------------------------------------------------------------------

// Operand stored row-major with K contiguous (NT-style operand).
// Loads a [TILE rows x KT k] tile into sm[k][row].
__device__ __forceinline__ void load_kcontig_tile(
    const float* __restrict__ base, int ld, int row0, int kb,
    float (*sm)[TILE], int tid)
{
#pragma unroll
    for (int l = 0; l < 2; ++l) {
        int idx = tid + l * 256;           // 0..511
        int r   = idx >> 2;                // 0..127
        int kq  = (idx & 3) * 4;           // 0,4,8,12
        const float4 v = *reinterpret_cast<const float4*>(
            base + (size_t)(row0 + r) * ld + kb + kq);
        sm[kq + 0][r] = v.x;
        sm[kq + 1][r] = v.y;
        sm[kq + 2][r] = v.z;
        sm[kq + 3][r] = v.w;
    }
}

// Operand stored row-major with N contiguous (NN-style B operand).
// Loads a [KT k x TILE n] tile into sm[k][n].
__device__ __forceinline__ void load_ncontig_tile(
    const float* __restrict__ base, int ld, int kb, int n0,
    float (*sm)[TILE], int tid)
{
#pragma unroll
    for (int l = 0; l < 2; ++l) {
        int idx = tid + l * 256;           // 0..511
        int k   = idx >> 5;                // 0..15
        int nq  = (idx & 31) * 4;          // 0..124
        *reinterpret_cast<float4*>(&sm[k][nq]) =
            *reinterpret_cast<const float4*>(base + (size_t)(kb + k) * ld + n0 + nq);
    }
}

// 8x8 per-thread FMA micro-kernel over one KT slice
__device__ __forceinline__ void mma_tile(
    const float (*As)[TILE], const float (*Bs)[TILE],
    float acc[8][8], int ty, int tx)
{
#pragma unroll
    for (int kk = 0; kk < KT; ++kk) {
        float a[8], bv[8];
#pragma unroll
        for (int i = 0; i < 8; ++i) a[i]  = As[kk][ty * 8 + i];
#pragma unroll
        for (int j = 0; j < 8; ++j) bv[j] = Bs[kk][tx * 8 + j];
#pragma unroll
        for (int i = 0; i < 8; ++i)
#pragma unroll
            for (int j = 0; j < 8; ++j)
                acc[i][j] = fmaf(a[i], bv[j], acc[i][j]);
    }
}

// ---------------------------------------------------------------------------
// GEMM1: scores[b][t][s] = sum_h dec[t,b,h] * ctxt[s,b,h]   (NT, batched)
// ---------------------------------------------------------------------------
__global__ __launch_bounds__(256, 2)
void gemm_scores(const float* __restrict__ dec,
                 const float* __restrict__ ctxt,
                 float* __restrict__ scores)
{
    __shared__ float As[KT][TILE];
    __shared__ float Bs[KT][TILE];

    const int b   = blockIdx.z;
    const int m0  = blockIdx.y * TILE;   // t tile
    const int n0  = blockIdx.x * TILE;   // s tile
    const int tid = threadIdx.x;
    const int ty  = tid >> 4, tx = tid & 15;

    const float* A  = dec  + b * HID;    // rows along t, stride LDA, k along h
    const float* Bm = ctxt + b * HID;    // rows along s, stride LDA, k along h

    float acc[8][8] = {};

    for (int kb = 0; kb < HID; kb += KT) {
        load_kcontig_tile(A,  LDA, m0, kb, As, tid);
        load_kcontig_tile(Bm, LDA, n0, kb, Bs, tid);
        __syncthreads();
        mma_tile(As, Bs, acc, ty, tx);
        __syncthreads();
    }

    float* C = scores + (size_t)b * TLEN * SLEN;
#pragma unroll
    for (int i = 0; i < 8; ++i) {
        float4* crow = reinterpret_cast<float4*>(
            C + (size_t)(m0 + ty * 8 + i) * SLEN + n0 + tx * 8);
        crow[0] = make_float4(acc[i][0], acc[i][1], acc[i][2], acc[i][3]);
        crow[1] = make_float4(acc[i][4], acc[i][5], acc[i][6], acc[i][7]);
    }
}

// ---------------------------------------------------------------------------
// Masked softmax over S, in place. One block per (b, t) row; row lives in regs.
// src_length buffer may be int32[NB] or int64[NB] (JAX x64 flag dependent).
// Little-endian discrimination: word[1]==0  <=>  int64 layout (high word of
// entry 0), since valid lengths are >= SLEN/2 = 1024 and never 0.
// ---------------------------------------------------------------------------
__global__ __launch_bounds__(256)
void softmax_rows(float* __restrict__ scores, const int* __restrict__ slen32)
{
    __shared__ float red[256];
    __shared__ int   s_len;

    const int row = blockIdx.x;          // b*TLEN + t
    const int b   = row / TLEN;
    const int tid = threadIdx.x;

    if (tid == 0) {
        const bool is64 = (slen32[1] == 0);
        int len = is64 ? slen32[2 * b] : slen32[b];
        if (len < 1)    len = 1;         // defensive clamp: never all-masked
        if (len > SLEN) len = SLEN;
        s_len = len;
    }
    __syncthreads();
    const int len = s_len;

    float* p = scores + (size_t)row * SLEN;
    float4 v0 = reinterpret_cast<const float4*>(p)[tid];
    float4 v1 = reinterpret_cast<const float4*>(p)[tid + 256];

    float e[8] = { v0.x, v0.y, v0.z, v0.w, v1.x, v1.y, v1.z, v1.w };
    int   s[8];
#pragma unroll
    for (int q = 0; q < 4; ++q) { s[q] = tid * 4 + q; s[4 + q] = (tid + 256) * 4 + q; }

    // row max over valid entries
    float m = -1e30f;
#pragma unroll
    for (int q = 0; q < 8; ++q) if (s[q] < len) m = fmaxf(m, e[q]);
    red[tid] = m; __syncthreads();
    for (int off = 128; off > 0; off >>= 1) {
        if (tid < off) red[tid] = fmaxf(red[tid], red[tid + off]);
        __syncthreads();
    }
    const float rowmax = red[0];
    __syncthreads();

    // exp & sum
    float sum = 0.f;
#pragma unroll
    for (int q = 0; q < 8; ++q) {
        float ev = (s[q] < len) ? expf(e[q] - rowmax) : 0.f;
        e[q] = ev;
        sum += ev;
    }
    red[tid] = sum; __syncthreads();
    for (int off = 128; off > 0; off >>= 1) {
        if (tid < off) red[tid] += red[tid + off];
        __syncthreads();
    }
    const float inv = 1.f / red[0];

    v0 = make_float4(e[0] * inv, e[1] * inv, e[2] * inv, e[3] * inv);
    v1 = make_float4(e[4] * inv, e[5] * inv, e[6] * inv, e[7] * inv);
    reinterpret_cast<float4*>(p)[tid]       = v0;
    reinterpret_cast<float4*>(p)[tid + 256] = v1;
}

// ---------------------------------------------------------------------------
// GEMM2: ctx[t,b,h] = sum_s attn[b,t,s] * ctxt[s,b,h]   (NN, batched)
// C written to g_ctx with row m = t*NB + b -> base g_ctx + b*HID, ldc = LDA
// ---------------------------------------------------------------------------
__global__ __launch_bounds__(256, 2)
void gemm_ctx(const float* __restrict__ attn,
              const float* __restrict__ ctxt)
{
    __shared__ float As[KT][TILE];
    __shared__ float Bs[KT][TILE];

    const int b   = blockIdx.z;
    const int m0  = blockIdx.y * TILE;   // t tile
    const int n0  = blockIdx.x * TILE;   // h tile
    const int tid = threadIdx.x;
    const int ty  = tid >> 4, tx = tid & 15;

    const float* A  = attn + (size_t)b * TLEN * SLEN;  // rows t, k along s (contig)
    const float* Bm = ctxt + b * HID;                  // k along s (stride LDA), n along h

    float acc[8][8] = {};

    for (int kb = 0; kb < SLEN; kb += KT) {
        load_kcontig_tile(A, SLEN, m0, kb, As, tid);
        load_ncontig_tile(Bm, LDA, kb, n0, Bs, tid);
        __syncthreads();
        mma_tile(As, Bs, acc, ty, tx);
        __syncthreads();
    }

    float* C = g_ctx + b * HID;
#pragma unroll
    for (int i = 0; i < 8; ++i) {
        float4* crow = reinterpret_cast<float4*>(
            C + (size_t)(m0 + ty * 8 + i) * LDA + n0 + tx * 8);
        crow[0] = make_float4(acc[i][0], acc[i][1], acc[i][2], acc[i][3]);
        crow[1] = make_float4(acc[i][4], acc[i][5], acc[i][6], acc[i][7]);
    }
}

// ---------------------------------------------------------------------------
// GEMM3: states[m,h] = tanh( sum_f concat(ctx,dec)[m,f] * W[h,f] + b[h] )
// m = t*NB + b (32768 rows). A k-tiles live wholly in one half (HID % KT == 0).
// ---------------------------------------------------------------------------
__global__ __launch_bounds__(256, 2)
void gemm_out(const float* __restrict__ dec,
              const float* __restrict__ W,
              const float* __restrict__ bias,
              float* __restrict__ out)
{
    __shared__ float As[KT][TILE];
    __shared__ float Bs[KT][TILE];

    const int m0  = blockIdx.y * TILE;
    const int n0  = blockIdx.x * TILE;
    const int tid = threadIdx.x;
    const int ty  = tid >> 4, tx = tid & 15;

    float acc[8][8] = {};

    for (int kb = 0; kb < 2 * HID; kb += KT) {
        const float* Ab;
        int ko;
        if (kb < HID) { Ab = g_ctx; ko = kb; }
        else          { Ab = dec;   ko = kb - HID; }
        load_kcontig_tile(Ab, HID, m0, ko, As, tid);
        load_kcontig_tile(W, 2 * HID, n0, kb, Bs, tid);
        __syncthreads();
        mma_tile(As, Bs, acc, ty, tx);
        __syncthreads();
    }

#pragma unroll
    for (int i = 0; i < 8; ++i) {
        const int r = m0 + ty * 8 + i;
        float v[8];
#pragma unroll
        for (int j = 0; j < 8; ++j) {
            const int c = n0 + tx * 8 + j;
            v[j] = tanhf(acc[i][j] + bias[c]);
        }
        float4* crow = reinterpret_cast<float4*>(out + (size_t)r * HID + n0 + tx * 8);
        crow[0] = make_float4(v[0], v[1], v[2], v[3]);
        crow[1] = make_float4(v[4], v[5], v[6], v[7]);
    }
}

// ---------------------------------------------------------------------------
// kernel_launch
//   Inputs are identified BY ELEMENT COUNT (robust to metadata ordering):
//     context  f32 [S,B,H]  -> 67108864
//     src_len  int [B]      -> 32   (int32 or int64; detected in-kernel)
//     dec      f32 [T,B,H]  -> 33554432
//     W        f32 [H,2H]   -> 2097152
//     bias     f32 [H]      -> 1024
//   output: states f32 [T,B,H] followed by attn f32 [B,T,S]
// ---------------------------------------------------------------------------
extern "C" void kernel_launch(void* const* d_in, const int* in_sizes, int n_in,
                              void* d_out, int out_size)
{
    const float* ctxt = nullptr;
    const int*   slen = nullptr;
    const float* dec  = nullptr;
    const float* W    = nullptr;
    const float* bias = nullptr;

    for (int i = 0; i < n_in; ++i) {
        switch (in_sizes[i]) {
            case SLEN * NB * HID: ctxt = (const float*)d_in[i]; break; // 67108864
            case TLEN * NB * HID: dec  = (const float*)d_in[i]; break; // 33554432
            case HID * 2 * HID:   W    = (const float*)d_in[i]; break; // 2097152
            case HID:             bias = (const float*)d_in[i]; break; // 1024
            case NB:              slen = (const int*)d_in[i];   break; // 32
        }
    }

    float* out    = (float*)d_out;
    float* states = out;                                  // [T,B,H]
    float* attn   = out + (size_t)TLEN * NB * HID;        // [B,T,S]

    dim3 blk(256);

    // 1) raw scores into the attn output region (used as scratch, softmaxed in place)
    gemm_scores<<<dim3(SLEN / TILE, TLEN / TILE, NB), blk>>>(dec, ctxt, attn);

    // 2) masked softmax over S, in place (dtype-robust length read)
    softmax_rows<<<NB * TLEN, 256>>>(attn, slen);

    // 3) ctx = attn @ enc  -> g_ctx scratch
    gemm_ctx<<<dim3(HID / TILE, TLEN / TILE, NB), blk>>>(attn, ctxt);

    // 4) states = tanh(concat(ctx, dec) @ W^T + b)
    gemm_out<<<dim3(HID / TILE, (TLEN * NB) / TILE), blk>>>(dec, W, bias, states);
}

// round 4
// speedup vs baseline: 2.6426x; 2.6426x over previous
#include <cuda_runtime.h>
#include <cuda_bf16.h>
#include <math.h>

// Problem constants (fixed by the dataset)
#define SLEN 2048
#define TLEN 1024
#define NB   32
#define HID  1024
#define LDA  (NB * HID)

typedef __nv_bfloat16 bf16;
typedef __nv_bfloat162 bf162;

// ---------------------------------------------------------------------------
// Scratch (static __device__; no runtime allocation)
// ---------------------------------------------------------------------------
__device__ bf16 g_enc_hi[(size_t)SLEN * NB * HID];
__device__ bf16 g_enc_lo[(size_t)SLEN * NB * HID];
__device__ bf16 g_dec_hi[(size_t)TLEN * NB * HID];
__device__ bf16 g_dec_lo[(size_t)TLEN * NB * HID];
__device__ bf16 g_W_hi[(size_t)HID * 2 * HID];
__device__ bf16 g_W_lo[(size_t)HID * 2 * HID];
__device__ bf16 g_attn_hi[(size_t)NB * TLEN * SLEN];
__device__ bf16 g_attn_lo[(size_t)NB * TLEN * SLEN];
__device__ bf16 g_ctx_hi[(size_t)TLEN * NB * HID];
__device__ bf16 g_ctx_lo[(size_t)TLEN * NB * HID];

// ---------------------------------------------------------------------------
// fp32 -> (bf16 hi, bf16 lo) split, vectorized by 4
// ---------------------------------------------------------------------------
__global__ void split_kernel(const float4* __restrict__ x,
                             bf162* __restrict__ hi, bf162* __restrict__ lo, int n4)
{
    int i = blockIdx.x * blockDim.x + threadIdx.x;
    if (i >= n4) return;
    float4 v = x[i];
    bf16 h0 = __float2bfloat16(v.x), h1 = __float2bfloat16(v.y);
    bf16 h2 = __float2bfloat16(v.z), h3 = __float2bfloat16(v.w);
    bf16 l0 = __float2bfloat16(v.x - __bfloat162float(h0));
    bf16 l1 = __float2bfloat16(v.y - __bfloat162float(h1));
    bf16 l2 = __float2bfloat16(v.z - __bfloat162float(h2));
    bf16 l3 = __float2bfloat16(v.w - __bfloat162float(h3));
    hi[2 * i]     = __halves2bfloat162(h0, h1);
    hi[2 * i + 1] = __halves2bfloat162(h2, h3);
    lo[2 * i]     = __halves2bfloat162(l0, l1);
    lo[2 * i + 1] = __halves2bfloat162(l2, l3);
}

// ---------------------------------------------------------------------------
// mma.sync / ldmatrix primitives
// ---------------------------------------------------------------------------
__device__ __forceinline__ unsigned smem_u32(const void* p) {
    return (unsigned)__cvta_generic_to_shared(p);
}

__device__ __forceinline__ void ldsm4(unsigned addr,
    unsigned& r0, unsigned& r1, unsigned& r2, unsigned& r3)
{
    asm volatile("ldmatrix.sync.aligned.m8n8.x4.shared.b16 {%0,%1,%2,%3}, [%4];"
        : "=r"(r0), "=r"(r1), "=r"(r2), "=r"(r3) : "r"(addr));
}

__device__ __forceinline__ void ldsm4t(unsigned addr,
    unsigned& r0, unsigned& r1, unsigned& r2, unsigned& r3)
{
    asm volatile("ldmatrix.sync.aligned.m8n8.x4.trans.shared.b16 {%0,%1,%2,%3}, [%4];"
        : "=r"(r0), "=r"(r1), "=r"(r2), "=r"(r3) : "r"(addr));
}

__device__ __forceinline__ void mma_bf16(float c[4],
    unsigned a0, unsigned a1, unsigned a2, unsigned a3, unsigned b0, unsigned b1)
{
    asm volatile(
        "mma.sync.aligned.m16n8k16.row.col.f32.bf16.bf16.f32 "
        "{%0,%1,%2,%3}, {%4,%5,%6,%7}, {%8,%9}, {%0,%1,%2,%3};"
        : "+f"(c[0]), "+f"(c[1]), "+f"(c[2]), "+f"(c[3])
        : "r"(a0), "r"(a1), "r"(a2), "r"(a3), "r"(b0), "r"(b1));
}

// Tile strides in elements (padded for conflict-free ldmatrix)
#define ASTR 40     // 32 k + 8 pad; row = 80B
#define BKSTR 136   // 128 n + 8 pad; row = 272B

// ---------------------------------------------------------------------------
// Global -> smem tile loaders (bf16 operands, 16B vectors)
// ---------------------------------------------------------------------------
// k-contiguous operand: tile [128 rows][32 k] -> dst[row*ASTR + k]
__device__ __forceinline__ void load_nt(bf16* __restrict__ dst,
    const bf16* __restrict__ src, int ld, int row0, int kb, int tid)
{
#pragma unroll
    for (int l = 0; l < 2; ++l) {
        int idx = tid + l * 256;
        int r = idx >> 2, q = idx & 3;
        uint4 v = *reinterpret_cast<const uint4*>(src + (size_t)(row0 + r) * ld + kb + q * 8);
        *reinterpret_cast<uint4*>(dst + r * ASTR + q * 8) = v;
    }
}

// n-contiguous operand (k-major tile): tile [32 k][128 n] -> dst[k*BKSTR + n]
__device__ __forceinline__ void load_tr(bf16* __restrict__ dst,
    const bf16* __restrict__ src, int ld, int kb, int n0, int tid)
{
#pragma unroll
    for (int l = 0; l < 2; ++l) {
        int idx = tid + l * 256;
        int r = idx >> 4, q = idx & 15;
        uint4 v = *reinterpret_cast<const uint4*>(src + (size_t)(kb + r) * ld + n0 + q * 8);
        *reinterpret_cast<uint4*>(dst + r * BKSTR + q * 8) = v;
    }
}

// ---------------------------------------------------------------------------
// One 32-wide K chunk of 3-term split MMAs.
// Warp tile 64x32: warp_m = wid>>2 (m_base 64*wm), warp_n = wid&3 (n_base 32*wn).
// acc[i][j] -> m-tile (16) i in 0..3, n-tile (8) j in 0..3.
// BT=false: B in [n][k] smem (stride ASTR). BT=true: B in [k][n] smem (BKSTR).
// ---------------------------------------------------------------------------
template <bool BT>
__device__ __forceinline__ void mma_chunk(
    const bf16* As_hi, const bf16* As_lo,
    const bf16* Bs_hi, const bf16* Bs_lo,
    float acc[4][4][4], int lane, int m_base, int n_base)
{
    const int ra = (lane & 7) + ((lane >> 3) & 1) * 8;   // A row-in-tile
    const int ka = (lane >> 4) * 8;                      // A k-half
    const int rb = (lane & 7) + (lane >> 4) * 8;         // B(NT) n row
    const int kbo = ((lane >> 3) & 1) * 8;               // B(NT) k-half
    const int krt = (lane & 7) + ((lane >> 3) & 1) * 8;  // B(TR) k row
    const int nft = (lane >> 4) * 8;                     // B(TR) n off

#pragma unroll
    for (int kk = 0; kk < 32; kk += 16) {
        unsigned ah[4][4], al[4][4], bh[2][4], bl[2][4];
#pragma unroll
        for (int i = 0; i < 4; ++i) {
            unsigned off = ((m_base + 16 * i + ra) * ASTR + kk + ka) * 2;
            ldsm4(smem_u32(As_hi) + off, ah[i][0], ah[i][1], ah[i][2], ah[i][3]);
            ldsm4(smem_u32(As_lo) + off, al[i][0], al[i][1], al[i][2], al[i][3]);
        }
#pragma unroll
        for (int jB = 0; jB < 2; ++jB) {
            if (!BT) {
                unsigned off = ((n_base + 16 * jB + rb) * ASTR + kk + kbo) * 2;
                ldsm4(smem_u32(Bs_hi) + off, bh[jB][0], bh[jB][1], bh[jB][2], bh[jB][3]);
                ldsm4(smem_u32(Bs_lo) + off, bl[jB][0], bl[jB][1], bl[jB][2], bl[jB][3]);
            } else {
                unsigned off = ((kk + krt) * BKSTR + n_base + 16 * jB + nft) * 2;
                ldsm4t(smem_u32(Bs_hi) + off, bh[jB][0], bh[jB][1], bh[jB][2], bh[jB][3]);
                ldsm4t(smem_u32(Bs_lo) + off, bl[jB][0], bl[jB][1], bl[jB][2], bl[jB][3]);
            }
        }
#pragma unroll
        for (int i = 0; i < 4; ++i)
#pragma unroll
            for (int j = 0; j < 4; ++j) {
                const int jB = j >> 1, s = (j & 1) * 2;
                mma_bf16(acc[i][j], ah[i][0], ah[i][1], ah[i][2], ah[i][3], bh[jB][s], bh[jB][s + 1]);
                mma_bf16(acc[i][j], ah[i][0], ah[i][1], ah[i][2], ah[i][3], bl[jB][s], bl[jB][s + 1]);
                mma_bf16(acc[i][j], al[i][0], al[i][1], al[i][2], al[i][3], bh[jB][s], bh[jB][s + 1]);
            }
    }
}

// ---------------------------------------------------------------------------
// GEMM1: scores[b][t][s] = dec . enc (both k-contig along h). fp32 epilogue.
// ---------------------------------------------------------------------------
__global__ __launch_bounds__(256)
void gemm1_scores(float* __restrict__ scores)
{
    __shared__ __align__(16) bf16 As_hi[128 * ASTR], As_lo[128 * ASTR];
    __shared__ __align__(16) bf16 Bs_hi[128 * ASTR], Bs_lo[128 * ASTR];

    const int b = blockIdx.z, m0 = blockIdx.y * 128, n0 = blockIdx.x * 128;
    const int tid = threadIdx.x, lane = tid & 31, wid = tid >> 5;
    const int m_base = (wid >> 2) * 64, n_base = (wid & 3) * 32;

    const bf16* Ah = g_dec_hi + b * HID;
    const bf16* Al = g_dec_lo + b * HID;
    const bf16* Bh = g_enc_hi + b * HID;
    const bf16* Bl = g_enc_lo + b * HID;

    float acc[4][4][4] = {};
    for (int kb = 0; kb < HID; kb += 32) {
        load_nt(As_hi, Ah, LDA, m0, kb, tid);
        load_nt(As_lo, Al, LDA, m0, kb, tid);
        load_nt(Bs_hi, Bh, LDA, n0, kb, tid);
        load_nt(Bs_lo, Bl, LDA, n0, kb, tid);
        __syncthreads();
        mma_chunk<false>(As_hi, As_lo, Bs_hi, Bs_lo, acc, lane, m_base, n_base);
        __syncthreads();
    }

    float* C = scores + (size_t)b * TLEN * SLEN;
    const int r0 = lane >> 2, c0 = (lane & 3) * 2;
#pragma unroll
    for (int i = 0; i < 4; ++i)
#pragma unroll
        for (int j = 0; j < 4; ++j) {
            const int row = m0 + m_base + 16 * i + r0;
            const int col = n0 + n_base + 8 * j + c0;
            *reinterpret_cast<float2*>(C + (size_t)row * SLEN + col)
                = make_float2(acc[i][j][0], acc[i][j][1]);
            *reinterpret_cast<float2*>(C + (size_t)(row + 8) * SLEN + col)
                = make_float2(acc[i][j][2], acc[i][j][3]);
        }
}

// ---------------------------------------------------------------------------
// Masked softmax over S, in place; also emits bf16 hi/lo split of attn.
// src_length may be int32[NB] or int64[NB]; word[1]==0 <=> int64 layout.
// ---------------------------------------------------------------------------
__global__ __launch_bounds__(256)
void softmax_rows(float* __restrict__ scores, const int* __restrict__ slen32)
{
    __shared__ float red[256];
    __shared__ int s_len;

    const int row = blockIdx.x;
    const int b = row / TLEN;
    const int tid = threadIdx.x;

    if (tid == 0) {
        const bool is64 = (slen32[1] == 0);
        int len = is64 ? slen32[2 * b] : slen32[b];
        if (len < 1) len = 1;
        if (len > SLEN) len = SLEN;
        s_len = len;
    }
    __syncthreads();
    const int len = s_len;

    float* p = scores + (size_t)row * SLEN;
    float4 v0 = reinterpret_cast<const float4*>(p)[tid];
    float4 v1 = reinterpret_cast<const float4*>(p)[tid + 256];

    float e[8] = { v0.x, v0.y, v0.z, v0.w, v1.x, v1.y, v1.z, v1.w };
    int s[8];
#pragma unroll
    for (int q = 0; q < 4; ++q) { s[q] = tid * 4 + q; s[4 + q] = (tid + 256) * 4 + q; }

    float m = -1e30f;
#pragma unroll
    for (int q = 0; q < 8; ++q) if (s[q] < len) m = fmaxf(m, e[q]);
    red[tid] = m; __syncthreads();
    for (int off = 128; off > 0; off >>= 1) {
        if (tid < off) red[tid] = fmaxf(red[tid], red[tid + off]);
        __syncthreads();
    }
    const float rowmax = red[0];
    __syncthreads();

    float sum = 0.f;
#pragma unroll
    for (int q = 0; q < 8; ++q) {
        float ev = (s[q] < len) ? expf(e[q] - rowmax) : 0.f;
        e[q] = ev; sum += ev;
    }
    red[tid] = sum; __syncthreads();
    for (int off = 128; off > 0; off >>= 1) {
        if (tid < off) red[tid] += red[tid + off];
        __syncthreads();
    }
    const float inv = 1.f / red[0];

#pragma unroll
    for (int q = 0; q < 8; ++q) e[q] *= inv;

    reinterpret_cast<float4*>(p)[tid]       = make_float4(e[0], e[1], e[2], e[3]);
    reinterpret_cast<float4*>(p)[tid + 256] = make_float4(e[4], e[5], e[6], e[7]);

    // bf16 hi/lo split of attn
    bf162* ph = reinterpret_cast<bf162*>(g_attn_hi + (size_t)row * SLEN);
    bf162* pl = reinterpret_cast<bf162*>(g_attn_lo + (size_t)row * SLEN);
#pragma unroll
    for (int h = 0; h < 2; ++h) {
        const int base = (h == 0) ? tid * 2 : (tid + 256) * 2;
        const int qb = h * 4;
        bf16 h0 = __float2bfloat16(e[qb + 0]), h1 = __float2bfloat16(e[qb + 1]);
        bf16 h2 = __float2bfloat16(e[qb + 2]), h3 = __float2bfloat16(e[qb + 3]);
        ph[base]     = __halves2bfloat162(h0, h1);
        ph[base + 1] = __halves2bfloat162(h2, h3);
        pl[base] = __halves2bfloat162(
            __float2bfloat16(e[qb + 0] - __bfloat162float(h0)),
            __float2bfloat16(e[qb + 1] - __bfloat162float(h1)));
        pl[base + 1] = __halves2bfloat162(
            __float2bfloat16(e[qb + 2] - __bfloat162float(h2)),
            __float2bfloat16(e[qb + 3] - __bfloat162float(h3)));
    }
}

// ---------------------------------------------------------------------------
// GEMM2: ctx[t(,b)][h] = attn . enc.  A k-contig (s), B n-contig (h) -> trans path.
// Epilogue: bf16 hi/lo split into g_ctx_{hi,lo} at layout [t*NB+b][HID].
// ---------------------------------------------------------------------------
__global__ __launch_bounds__(256)
void gemm2_ctx()
{
    __shared__ __align__(16) bf16 As_hi[128 * ASTR], As_lo[128 * ASTR];
    __shared__ __align__(16) bf16 Bs_hi[32 * BKSTR], Bs_lo[32 * BKSTR];

    const int b = blockIdx.z, m0 = blockIdx.y * 128, n0 = blockIdx.x * 128;
    const int tid = threadIdx.x, lane = tid & 31, wid = tid >> 5;
    const int m_base = (wid >> 2) * 64, n_base = (wid & 3) * 32;

    const bf16* Ah = g_attn_hi + (size_t)b * TLEN * SLEN;
    const bf16* Al = g_attn_lo + (size_t)b * TLEN * SLEN;
    const bf16* Bh = g_enc_hi + b * HID;
    const bf16* Bl = g_enc_lo + b * HID;

    float acc[4][4][4] = {};
    for (int kb = 0; kb < SLEN; kb += 32) {
        load_nt(As_hi, Ah, SLEN, m0, kb, tid);
        load_nt(As_lo, Al, SLEN, m0, kb, tid);
        load_tr(Bs_hi, Bh, LDA, kb, n0, tid);
        load_tr(Bs_lo, Bl, LDA, kb, n0, tid);
        __syncthreads();
        mma_chunk<true>(As_hi, As_lo, Bs_hi, Bs_lo, acc, lane, m_base, n_base);
        __syncthreads();
    }

    const int r0 = lane >> 2, c0 = (lane & 3) * 2;
#pragma unroll
    for (int i = 0; i < 4; ++i)
#pragma unroll
        for (int j = 0; j < 4; ++j) {
            const int mrow = m0 + m_base + 16 * i + r0;  // t index
            const int col = n0 + n_base + 8 * j + c0;    // h index
#pragma unroll
            for (int hh = 0; hh < 2; ++hh) {
                const size_t off = (size_t)b * HID + (size_t)(mrow + 8 * hh) * LDA + col;
                const float va = acc[i][j][2 * hh], vb = acc[i][j][2 * hh + 1];
                bf16 ha = __float2bfloat16(va), hb = __float2bfloat16(vb);
                *reinterpret_cast<bf162*>(g_ctx_hi + off) = __halves2bfloat162(ha, hb);
                *reinterpret_cast<bf162*>(g_ctx_lo + off) = __halves2bfloat162(
                    __float2bfloat16(va - __bfloat162float(ha)),
                    __float2bfloat16(vb - __bfloat162float(hb)));
            }
        }
}

// ---------------------------------------------------------------------------
// GEMM3: states[m][h] = tanh( concat(ctx,dec)[m][:] . W[h][:] + bias[h] )
// m = t*NB+b (32768 rows). K = 2048 (first 1024 from ctx, second from dec).
// ---------------------------------------------------------------------------
__global__ __launch_bounds__(256)
void gemm3_out(const float* __restrict__ bias, float* __restrict__ out)
{
    __shared__ __align__(16) bf16 As_hi[128 * ASTR], As_lo[128 * ASTR];
    __shared__ __align__(16) bf16 Bs_hi[128 * ASTR], Bs_lo[128 * ASTR];

    const int m0 = blockIdx.y * 128, n0 = blockIdx.x * 128;
    const int tid = threadIdx.x, lane = tid & 31, wid = tid >> 5;
    const int m_base = (wid >> 2) * 64, n_base = (wid & 3) * 32;

    float acc[4][4][4] = {};
    for (int kb = 0; kb < 2 * HID; kb += 32) {
        const bf16* Ah; const bf16* Al; int ko;
        if (kb < HID) { Ah = g_ctx_hi; Al = g_ctx_lo; ko = kb; }
        else          { Ah = g_dec_hi; Al = g_dec_lo; ko = kb - HID; }
        load_nt(As_hi, Ah, HID, m0, ko, tid);
        load_nt(As_lo, Al, HID, m0, ko, tid);
        load_nt(Bs_hi, g_W_hi, 2 * HID, n0, kb, tid);
        load_nt(Bs_lo, g_W_lo, 2 * HID, n0, kb, tid);
        __syncthreads();
        mma_chunk<false>(As_hi, As_lo, Bs_hi, Bs_lo, acc, lane, m_base, n_base);
        __syncthreads();
    }

    const int r0 = lane >> 2, c0 = (lane & 3) * 2;
#pragma unroll
    for (int i = 0; i < 4; ++i)
#pragma unroll
        for (int j = 0; j < 4; ++j) {
            const int row = m0 + m_base + 16 * i + r0;
            const int col = n0 + n_base + 8 * j + c0;
            const float b0 = bias[col], b1 = bias[col + 1];
            *reinterpret_cast<float2*>(out + (size_t)row * HID + col)
                = make_float2(tanhf(acc[i][j][0] + b0), tanhf(acc[i][j][1] + b1));
            *reinterpret_cast<float2*>(out + (size_t)(row + 8) * HID + col)
                = make_float2(tanhf(acc[i][j][2] + b0), tanhf(acc[i][j][3] + b1));
        }
}

// ---------------------------------------------------------------------------
// kernel_launch — inputs identified by element count (order-proof)
// ---------------------------------------------------------------------------
extern "C" void kernel_launch(void* const* d_in, const int* in_sizes, int n_in,
                              void* d_out, int out_size)
{
    const float* ctxt = nullptr;
    const int*   slen = nullptr;
    const float* dec  = nullptr;
    const float* W    = nullptr;
    const float* bias = nullptr;

    for (int i = 0; i < n_in; ++i) {
        switch (in_sizes[i]) {
            case SLEN * NB * HID: ctxt = (const float*)d_in[i]; break;
            case TLEN * NB * HID: dec  = (const float*)d_in[i]; break;
            case HID * 2 * HID:   W    = (const float*)d_in[i]; break;
            case HID:             bias = (const float*)d_in[i]; break;
            case NB:              slen = (const int*)d_in[i];   break;
        }
    }

    float* out    = (float*)d_out;
    float* states = out;                              // [T,B,H]
    float* attn   = out + (size_t)TLEN * NB * HID;    // [B,T,S]

    bf16 *enc_hi, *enc_lo, *dec_hi, *dec_lo, *w_hi, *w_lo;
    cudaGetSymbolAddress((void**)&enc_hi, g_enc_hi);
    cudaGetSymbolAddress((void**)&enc_lo, g_enc_lo);
    cudaGetSymbolAddress((void**)&dec_hi, g_dec_hi);
    cudaGetSymbolAddress((void**)&dec_lo, g_dec_lo);
    cudaGetSymbolAddress((void**)&w_hi,  g_W_hi);
    cudaGetSymbolAddress((void**)&w_lo,  g_W_lo);

    // 1) fp32 -> bf16 hi/lo splits
    {
        int n4 = (SLEN * NB * HID) / 4;
        split_kernel<<<n4 / 256, 256>>>((const float4*)ctxt, (bf162*)enc_hi, (bf162*)enc_lo, n4);
        n4 = (TLEN * NB * HID) / 4;
        split_kernel<<<n4 / 256, 256>>>((const float4*)dec, (bf162*)dec_hi, (bf162*)dec_lo, n4);
        n4 = (HID * 2 * HID) / 4;
        split_kernel<<<n4 / 256, 256>>>((const float4*)W, (bf162*)w_hi, (bf162*)w_lo, n4);
    }

    // 2) scores (bf16x3 tensor GEMM) -> attn output region
    gemm1_scores<<<dim3(SLEN / 128, TLEN / 128, NB), 256>>>(attn);

    // 3) masked softmax in place + attn hi/lo split
    softmax_rows<<<NB * TLEN, 256>>>(attn, slen);

    // 4) ctx = attn @ enc -> ctx hi/lo split
    gemm2_ctx<<<dim3(HID / 128, TLEN / 128, NB), 256>>>();

    // 5) states = tanh(concat(ctx,dec) @ W^T + b)
    gemm3_out<<<dim3(HID / 128, (TLEN * NB) / 128), 256>>>(bias, states);
}

// round 6
// speedup vs baseline: 2.7072x; 1.0244x over previous
#include <cuda_runtime.h>
#include <cuda_bf16.h>
#include <math.h>
#include <stdint.h>

#define SLEN 2048
#define TLEN 1024
#define NB   32
#define HID  1024
#define LDA  (NB * HID)

typedef __nv_bfloat16 bf16;
typedef __nv_bfloat162 bf162;

// ---------------------------------------------------------------------------
// Static scratch (no runtime allocation)
// ---------------------------------------------------------------------------
__device__ bf16 g_enc_hi [(size_t)SLEN * NB * HID];
__device__ bf16 g_enc_lo [(size_t)SLEN * NB * HID];
__device__ bf16 g_dec_hi [(size_t)TLEN * NB * HID];
__device__ bf16 g_dec_lo [(size_t)TLEN * NB * HID];
__device__ bf16 g_W_hi   [(size_t)HID * 2 * HID];
__device__ bf16 g_W_lo   [(size_t)HID * 2 * HID];
__device__ bf16 g_attn_hi[(size_t)NB * TLEN * SLEN];
__device__ bf16 g_attn_lo[(size_t)NB * TLEN * SLEN];
__device__ bf16 g_ctx_hi [(size_t)TLEN * NB * HID];   // [m=t*NB+b][h]
__device__ bf16 g_ctx_lo [(size_t)TLEN * NB * HID];

// ---------------------------------------------------------------------------
// fp32 -> (bf16 hi, bf16 lo) split
// ---------------------------------------------------------------------------
__global__ void split_kernel(const float4* __restrict__ x,
                             bf162* __restrict__ hi, bf162* __restrict__ lo, int n4)
{
    int i = blockIdx.x * blockDim.x + threadIdx.x;
    if (i >= n4) return;
    float4 v = x[i];
    bf16 h0 = __float2bfloat16(v.x), h1 = __float2bfloat16(v.y);
    bf16 h2 = __float2bfloat16(v.z), h3 = __float2bfloat16(v.w);
    hi[2 * i]     = __halves2bfloat162(h0, h1);
    hi[2 * i + 1] = __halves2bfloat162(h2, h3);
    lo[2 * i] = __halves2bfloat162(__float2bfloat16(v.x - __bfloat162float(h0)),
                                   __float2bfloat16(v.y - __bfloat162float(h1)));
    lo[2 * i + 1] = __halves2bfloat162(__float2bfloat16(v.z - __bfloat162float(h2)),
                                       __float2bfloat16(v.w - __bfloat162float(h3)));
}

// ---------------------------------------------------------------------------
// Primitives
// ---------------------------------------------------------------------------
__device__ __forceinline__ unsigned smem_u32(const void* p) {
    return (unsigned)__cvta_generic_to_shared(p);
}
__device__ __forceinline__ void cp16(unsigned dst, const void* src) {
    asm volatile("cp.async.cg.shared.global [%0], [%1], 16;" :: "r"(dst), "l"(src));
}
__device__ __forceinline__ void cp_commit() {
    asm volatile("cp.async.commit_group;" ::: "memory");
}
template <int N>
__device__ __forceinline__ void cp_wait() {
    asm volatile("cp.async.wait_group %0;" :: "n"(N) : "memory");
}

__device__ __forceinline__ void ldsm4(unsigned addr,
    unsigned& r0, unsigned& r1, unsigned& r2, unsigned& r3)
{
    asm volatile("ldmatrix.sync.aligned.m8n8.x4.shared.b16 {%0,%1,%2,%3}, [%4];"
        : "=r"(r0), "=r"(r1), "=r"(r2), "=r"(r3) : "r"(addr));
}
__device__ __forceinline__ void ldsm4t(unsigned addr,
    unsigned& r0, unsigned& r1, unsigned& r2, unsigned& r3)
{
    asm volatile("ldmatrix.sync.aligned.m8n8.x4.trans.shared.b16 {%0,%1,%2,%3}, [%4];"
        : "=r"(r0), "=r"(r1), "=r"(r2), "=r"(r3) : "r"(addr));
}
__device__ __forceinline__ void mma_bf16(float c[4],
    unsigned a0, unsigned a1, unsigned a2, unsigned a3, unsigned b0, unsigned b1)
{
    asm volatile(
        "mma.sync.aligned.m16n8k16.row.col.f32.bf16.bf16.f32 "
        "{%0,%1,%2,%3}, {%4,%5,%6,%7}, {%8,%9}, {%0,%1,%2,%3};"
        : "+f"(c[0]), "+f"(c[1]), "+f"(c[2]), "+f"(c[3])
        : "r"(a0), "r"(a1), "r"(a2), "r"(a3), "r"(b0), "r"(b1));
}

// Tile strides in elements (padded; row bytes are multiples of 16)
#define ASTR 40     // [row][32k]: 80B rows
#define BKSTR 136   // [32k][128n]: 272B rows

// Stage byte offsets (k-contig B variant: 4 tiles of 128*ASTR)
#define T_AH 0
#define T_AL 10240
#define T_BH 20480
#define T_BL 30720
#define STG_NT 40960
// trans-B variant (gemm2): B tiles are 32*BKSTR*2 = 8704 B
#define T2_BH 20480
#define T2_BL 29184
#define STG_TR 37888

// ---------------------------------------------------------------------------
// cp.async tile loaders
// ---------------------------------------------------------------------------
// k-contiguous tile: [128 rows][32 k] -> smem row*ASTR + k
__device__ __forceinline__ void cpa_nt(unsigned sb, const bf16* __restrict__ g,
                                       size_t ld, int tid)
{
#pragma unroll
    for (int l = 0; l < 2; ++l) {
        int idx = tid + l * 256;
        int r = idx >> 2, q = idx & 3;
        cp16(sb + (unsigned)(r * ASTR + q * 8) * 2, g + (size_t)r * ld + q * 8);
    }
}
// n-contiguous (k-major) tile: [32 k][128 n] -> smem k*BKSTR + n
__device__ __forceinline__ void cpa_tr(unsigned sb, const bf16* __restrict__ g,
                                       size_t ld, int tid)
{
#pragma unroll
    for (int l = 0; l < 2; ++l) {
        int idx = tid + l * 256;
        int r = idx >> 4, q = idx & 15;
        cp16(sb + (unsigned)(r * BKSTR + q * 8) * 2, g + (size_t)r * ld + q * 8);
    }
}

// ---------------------------------------------------------------------------
// One 32-wide K chunk of 3-term split MMAs (identical logic to round 4).
// ---------------------------------------------------------------------------
template <bool BT>
__device__ __forceinline__ void mma_chunk(
    const bf16* As_hi, const bf16* As_lo,
    const bf16* Bs_hi, const bf16* Bs_lo,
    float acc[4][4][4], int lane, int m_base, int n_base)
{
    const int ra = (lane & 7) + ((lane >> 3) & 1) * 8;
    const int ka = (lane >> 4) * 8;
    const int rb = (lane & 7) + (lane >> 4) * 8;
    const int kbo = ((lane >> 3) & 1) * 8;
    const int krt = (lane & 7) + ((lane >> 3) & 1) * 8;
    const int nft = (lane >> 4) * 8;

#pragma unroll
    for (int kk = 0; kk < 32; kk += 16) {
        unsigned ah[4][4], al[4][4], bh[2][4], bl[2][4];
#pragma unroll
        for (int i = 0; i < 4; ++i) {
            unsigned off = ((m_base + 16 * i + ra) * ASTR + kk + ka) * 2;
            ldsm4(smem_u32(As_hi) + off, ah[i][0], ah[i][1], ah[i][2], ah[i][3]);
            ldsm4(smem_u32(As_lo) + off, al[i][0], al[i][1], al[i][2], al[i][3]);
        }
#pragma unroll
        for (int jB = 0; jB < 2; ++jB) {
            if (!BT) {
                unsigned off = ((n_base + 16 * jB + rb) * ASTR + kk + kbo) * 2;
                ldsm4(smem_u32(Bs_hi) + off, bh[jB][0], bh[jB][1], bh[jB][2], bh[jB][3]);
                ldsm4(smem_u32(Bs_lo) + off, bl[jB][0], bl[jB][1], bl[jB][2], bl[jB][3]);
            } else {
                unsigned off = ((kk + krt) * BKSTR + n_base + 16 * jB + nft) * 2;
                ldsm4t(smem_u32(Bs_hi) + off, bh[jB][0], bh[jB][1], bh[jB][2], bh[jB][3]);
                ldsm4t(smem_u32(Bs_lo) + off, bl[jB][0], bl[jB][1], bl[jB][2], bl[jB][3]);
            }
        }
#pragma unroll
        for (int i = 0; i < 4; ++i)
#pragma unroll
            for (int j = 0; j < 4; ++j) {
                const int jB = j >> 1, s = (j & 1) * 2;
                mma_bf16(acc[i][j], ah[i][0], ah[i][1], ah[i][2], ah[i][3], bh[jB][s], bh[jB][s + 1]);
                mma_bf16(acc[i][j], ah[i][0], ah[i][1], ah[i][2], ah[i][3], bl[jB][s], bl[jB][s + 1]);
                mma_bf16(acc[i][j], al[i][0], al[i][1], al[i][2], al[i][3], bh[jB][s], bh[jB][s + 1]);
            }
    }
}

// ---------------------------------------------------------------------------
// GEMM1: scores[b][t][s] = dec . enc   (both operands k-contig along h)
// ---------------------------------------------------------------------------
__global__ __launch_bounds__(256, 2)
void gemm1_scores(float* __restrict__ scores)
{
    extern __shared__ __align__(16) char dsm[];
    const int b = blockIdx.z, m0 = blockIdx.y * 128, n0 = blockIdx.x * 128;
    const int tid = threadIdx.x, lane = tid & 31, wid = tid >> 5;
    const int m_base = (wid >> 2) * 64, n_base = (wid & 3) * 32;

    const unsigned sb = smem_u32(dsm);
    const unsigned st[2] = { sb, sb + STG_NT };

    const bf16* Ah = g_dec_hi + (size_t)m0 * LDA + (size_t)b * HID;
    const bf16* Al = g_dec_lo + (size_t)m0 * LDA + (size_t)b * HID;
    const bf16* Bh = g_enc_hi + (size_t)n0 * LDA + (size_t)b * HID;
    const bf16* Bl = g_enc_lo + (size_t)n0 * LDA + (size_t)b * HID;
    const int NC = HID / 32;  // 32

    cpa_nt(st[0] + T_AH, Ah, LDA, tid);
    cpa_nt(st[0] + T_AL, Al, LDA, tid);
    cpa_nt(st[0] + T_BH, Bh, LDA, tid);
    cpa_nt(st[0] + T_BL, Bl, LDA, tid);
    cp_commit();

    float acc[4][4][4] = {};
    for (int m = 0; m < NC; ++m) {
        const int s = m & 1;
        if (m + 1 < NC) {
            const int j = (m + 1) & 1;
            const size_t kb = (size_t)(m + 1) * 32;
            cpa_nt(st[j] + T_AH, Ah + kb, LDA, tid);
            cpa_nt(st[j] + T_AL, Al + kb, LDA, tid);
            cpa_nt(st[j] + T_BH, Bh + kb, LDA, tid);
            cpa_nt(st[j] + T_BL, Bl + kb, LDA, tid);
            cp_commit();
            cp_wait<1>();
        } else {
            cp_wait<0>();
        }
        __syncthreads();
        mma_chunk<false>((const bf16*)(dsm + (st[s] - sb) + T_AH),
                         (const bf16*)(dsm + (st[s] - sb) + T_AL),
                         (const bf16*)(dsm + (st[s] - sb) + T_BH),
                         (const bf16*)(dsm + (st[s] - sb) + T_BL),
                         acc, lane, m_base, n_base);
        __syncthreads();
    }

    float* C = scores + (size_t)b * TLEN * SLEN;
    const int r0 = lane >> 2, c0 = (lane & 3) * 2;
#pragma unroll
    for (int i = 0; i < 4; ++i)
#pragma unroll
        for (int j = 0; j < 4; ++j) {
            const int row = m0 + m_base + 16 * i + r0;
            const int col = n0 + n_base + 8 * j + c0;
            *reinterpret_cast<float2*>(C + (size_t)row * SLEN + col)
                = make_float2(acc[i][j][0], acc[i][j][1]);
            *reinterpret_cast<float2*>(C + (size_t)(row + 8) * SLEN + col)
                = make_float2(acc[i][j][2], acc[i][j][3]);
        }
}

// ---------------------------------------------------------------------------
// Masked softmax over S, in place; emits bf16 hi/lo split of attn.
// ---------------------------------------------------------------------------
__global__ __launch_bounds__(256)
void softmax_rows(float* __restrict__ scores, const int* __restrict__ slen32)
{
    __shared__ float red[256];
    __shared__ int s_len;

    const int row = blockIdx.x;
    const int b = row / TLEN;
    const int tid = threadIdx.x;

    if (tid == 0) {
        const bool is64 = (slen32[1] == 0);
        int len = is64 ? slen32[2 * b] : slen32[b];
        if (len < 1) len = 1;
        if (len > SLEN) len = SLEN;
        s_len = len;
    }
    __syncthreads();
    const int len = s_len;

    float* p = scores + (size_t)row * SLEN;
    float4 v0 = reinterpret_cast<const float4*>(p)[tid];
    float4 v1 = reinterpret_cast<const float4*>(p)[tid + 256];

    float e[8] = { v0.x, v0.y, v0.z, v0.w, v1.x, v1.y, v1.z, v1.w };
    int s[8];
#pragma unroll
    for (int q = 0; q < 4; ++q) { s[q] = tid * 4 + q; s[4 + q] = (tid + 256) * 4 + q; }

    float m = -1e30f;
#pragma unroll
    for (int q = 0; q < 8; ++q) if (s[q] < len) m = fmaxf(m, e[q]);
    red[tid] = m; __syncthreads();
    for (int off = 128; off > 0; off >>= 1) {
        if (tid < off) red[tid] = fmaxf(red[tid], red[tid + off]);
        __syncthreads();
    }
    const float rowmax = red[0];
    __syncthreads();

    float sum = 0.f;
#pragma unroll
    for (int q = 0; q < 8; ++q) {
        float ev = (s[q] < len) ? expf(e[q] - rowmax) : 0.f;
        e[q] = ev; sum += ev;
    }
    red[tid] = sum; __syncthreads();
    for (int off = 128; off > 0; off >>= 1) {
        if (tid < off) red[tid] += red[tid + off];
        __syncthreads();
    }
    const float inv = 1.f / red[0];

#pragma unroll
    for (int q = 0; q < 8; ++q) e[q] *= inv;

    reinterpret_cast<float4*>(p)[tid]       = make_float4(e[0], e[1], e[2], e[3]);
    reinterpret_cast<float4*>(p)[tid + 256] = make_float4(e[4], e[5], e[6], e[7]);

    bf162* phh = reinterpret_cast<bf162*>(g_attn_hi + (size_t)row * SLEN);
    bf162* pll = reinterpret_cast<bf162*>(g_attn_lo + (size_t)row * SLEN);
#pragma unroll
    for (int h = 0; h < 2; ++h) {
        const int base = (h == 0) ? tid * 2 : (tid + 256) * 2;
        const int qb = h * 4;
        bf16 h0 = __float2bfloat16(e[qb + 0]), h1 = __float2bfloat16(e[qb + 1]);
        bf16 h2 = __float2bfloat16(e[qb + 2]), h3 = __float2bfloat16(e[qb + 3]);
        phh[base]     = __halves2bfloat162(h0, h1);
        phh[base + 1] = __halves2bfloat162(h2, h3);
        pll[base] = __halves2bfloat162(
            __float2bfloat16(e[qb + 0] - __bfloat162float(h0)),
            __float2bfloat16(e[qb + 1] - __bfloat162float(h1)));
        pll[base + 1] = __halves2bfloat162(
            __float2bfloat16(e[qb + 2] - __bfloat162float(h2)),
            __float2bfloat16(e[qb + 3] - __bfloat162float(h3)));
    }
}

// ---------------------------------------------------------------------------
// GEMM2: ctx = attn . enc   (A k-contig along s; B n-contig -> trans path)
// Epilogue: bf16 hi/lo split into g_ctx at [t*NB+b][h]
// ---------------------------------------------------------------------------
__global__ __launch_bounds__(256, 2)
void gemm2_ctx()
{
    extern __shared__ __align__(16) char dsm[];
    const int b = blockIdx.z, m0 = blockIdx.y * 128, n0 = blockIdx.x * 128;
    const int tid = threadIdx.x, lane = tid & 31, wid = tid >> 5;
    const int m_base = (wid >> 2) * 64, n_base = (wid & 3) * 32;

    const unsigned sb = smem_u32(dsm);
    const unsigned st[2] = { sb, sb + STG_TR };

    const bf16* Ah = g_attn_hi + (size_t)b * TLEN * SLEN + (size_t)m0 * SLEN;
    const bf16* Al = g_attn_lo + (size_t)b * TLEN * SLEN + (size_t)m0 * SLEN;
    const bf16* Bh = g_enc_hi + (size_t)b * HID + n0;   // rows along s (stride LDA)
    const bf16* Bl = g_enc_lo + (size_t)b * HID + n0;
    const int NC = SLEN / 32;  // 64

    cpa_nt(st[0] + T_AH, Ah, SLEN, tid);
    cpa_nt(st[0] + T_AL, Al, SLEN, tid);
    cpa_tr(st[0] + T2_BH, Bh, LDA, tid);
    cpa_tr(st[0] + T2_BL, Bl, LDA, tid);
    cp_commit();

    float acc[4][4][4] = {};
    for (int m = 0; m < NC; ++m) {
        const int s = m & 1;
        if (m + 1 < NC) {
            const int j = (m + 1) & 1;
            const size_t kb = (size_t)(m + 1) * 32;
            cpa_nt(st[j] + T_AH, Ah + kb, SLEN, tid);
            cpa_nt(st[j] + T_AL, Al + kb, SLEN, tid);
            cpa_tr(st[j] + T2_BH, Bh + kb * LDA, LDA, tid);
            cpa_tr(st[j] + T2_BL, Bl + kb * LDA, LDA, tid);
            cp_commit();
            cp_wait<1>();
        } else {
            cp_wait<0>();
        }
        __syncthreads();
        mma_chunk<true>((const bf16*)(dsm + (st[s] - sb) + T_AH),
                        (const bf16*)(dsm + (st[s] - sb) + T_AL),
                        (const bf16*)(dsm + (st[s] - sb) + T2_BH),
                        (const bf16*)(dsm + (st[s] - sb) + T2_BL),
                        acc, lane, m_base, n_base);
        __syncthreads();
    }

    const int r0 = lane >> 2, c0 = (lane & 3) * 2;
#pragma unroll
    for (int i = 0; i < 4; ++i)
#pragma unroll
        for (int j = 0; j < 4; ++j) {
            const int mrow = m0 + m_base + 16 * i + r0;
            const int col = n0 + n_base + 8 * j + c0;
#pragma unroll
            for (int hh = 0; hh < 2; ++hh) {
                const size_t off = (size_t)b * HID + (size_t)(mrow + 8 * hh) * LDA + col;
                const float va = acc[i][j][2 * hh], vb = acc[i][j][2 * hh + 1];
                bf16 ha = __float2bfloat16(va), hb = __float2bfloat16(vb);
                *reinterpret_cast<bf162*>(g_ctx_hi + off) = __halves2bfloat162(ha, hb);
                *reinterpret_cast<bf162*>(g_ctx_lo + off) = __halves2bfloat162(
                    __float2bfloat16(va - __bfloat162float(ha)),
                    __float2bfloat16(vb - __bfloat162float(hb)));
            }
        }
}

// ---------------------------------------------------------------------------
// GEMM3: states = tanh(concat(ctx,dec) . W^T + bias)
// ---------------------------------------------------------------------------
__global__ __launch_bounds__(256, 2)
void gemm3_out(const float* __restrict__ bias, float* __restrict__ outp)
{
    extern __shared__ __align__(16) char dsm[];
    const int m0 = blockIdx.y * 128, n0 = blockIdx.x * 128;
    const int tid = threadIdx.x, lane = tid & 31, wid = tid >> 5;
    const int m_base = (wid >> 2) * 64, n_base = (wid & 3) * 32;

    const unsigned sb = smem_u32(dsm);
    const unsigned st[2] = { sb, sb + STG_NT };

    const bf16* CtxH = g_ctx_hi + (size_t)m0 * HID;
    const bf16* CtxL = g_ctx_lo + (size_t)m0 * HID;
    const bf16* DecH = g_dec_hi + (size_t)m0 * HID;
    const bf16* DecL = g_dec_lo + (size_t)m0 * HID;
    const bf16* Bh = g_W_hi + (size_t)n0 * (2 * HID);
    const bf16* Bl = g_W_lo + (size_t)n0 * (2 * HID);
    const int NC = (2 * HID) / 32;  // 64

    cpa_nt(st[0] + T_AH, CtxH, HID, tid);
    cpa_nt(st[0] + T_AL, CtxL, HID, tid);
    cpa_nt(st[0] + T_BH, Bh, 2 * HID, tid);
    cpa_nt(st[0] + T_BL, Bl, 2 * HID, tid);
    cp_commit();

    float acc[4][4][4] = {};
    for (int m = 0; m < NC; ++m) {
        const int s = m & 1;
        if (m + 1 < NC) {
            const int j = (m + 1) & 1;
            const int kb = (m + 1) * 32;
            const bf16* pah; const bf16* pal;
            if (kb < HID) { pah = CtxH + kb; pal = CtxL + kb; }
            else          { pah = DecH + (kb - HID); pal = DecL + (kb - HID); }
            cpa_nt(st[j] + T_AH, pah, HID, tid);
            cpa_nt(st[j] + T_AL, pal, HID, tid);
            cpa_nt(st[j] + T_BH, Bh + kb, 2 * HID, tid);
            cpa_nt(st[j] + T_BL, Bl + kb, 2 * HID, tid);
            cp_commit();
            cp_wait<1>();
        } else {
            cp_wait<0>();
        }
        __syncthreads();
        mma_chunk<false>((const bf16*)(dsm + (st[s] - sb) + T_AH),
                         (const bf16*)(dsm + (st[s] - sb) + T_AL),
                         (const bf16*)(dsm + (st[s] - sb) + T_BH),
                         (const bf16*)(dsm + (st[s] - sb) + T_BL),
                         acc, lane, m_base, n_base);
        __syncthreads();
    }

    const int r0 = lane >> 2, c0 = (lane & 3) * 2;
#pragma unroll
    for (int i = 0; i < 4; ++i)
#pragma unroll
        for (int j = 0; j < 4; ++j) {
            const int row = m0 + m_base + 16 * i + r0;
            const int col = n0 + n_base + 8 * j + c0;
            const float b0 = bias[col], b1 = bias[col + 1];
            *reinterpret_cast<float2*>(outp + (size_t)row * HID + col)
                = make_float2(tanhf(acc[i][j][0] + b0), tanhf(acc[i][j][1] + b1));
            *reinterpret_cast<float2*>(outp + (size_t)(row + 8) * HID + col)
                = make_float2(tanhf(acc[i][j][2] + b0), tanhf(acc[i][j][3] + b1));
        }
}

// ---------------------------------------------------------------------------
// kernel_launch — inputs identified by element count (order-proof)
// ---------------------------------------------------------------------------
extern "C" void kernel_launch(void* const* d_in, const int* in_sizes, int n_in,
                              void* d_out, int out_size)
{
    const float* ctxt = nullptr;
    const int*   slen = nullptr;
    const float* dec  = nullptr;
    const float* W    = nullptr;
    const float* bias = nullptr;

    for (int i = 0; i < n_in; ++i) {
        switch (in_sizes[i]) {
            case SLEN * NB * HID: ctxt = (const float*)d_in[i]; break;
            case TLEN * NB * HID: dec  = (const float*)d_in[i]; break;
            case HID * 2 * HID:   W    = (const float*)d_in[i]; break;
            case HID:             bias = (const float*)d_in[i]; break;
            case NB:              slen = (const int*)d_in[i];   break;
        }
    }

    float* outp   = (float*)d_out;
    float* states = outp;                              // [T,B,H]
    float* attn   = outp + (size_t)TLEN * NB * HID;    // [B,T,S]

    const int smem_nt = 2 * STG_NT;  // 81920
    const int smem_tr = 2 * STG_TR;  // 75776
    cudaFuncSetAttribute(gemm1_scores, cudaFuncAttributeMaxDynamicSharedMemorySize, smem_nt);
    cudaFuncSetAttribute(gemm2_ctx,    cudaFuncAttributeMaxDynamicSharedMemorySize, smem_tr);
    cudaFuncSetAttribute(gemm3_out,    cudaFuncAttributeMaxDynamicSharedMemorySize, smem_nt);

    bf16 *enc_hi, *enc_lo, *dec_hi, *dec_lo, *w_hi, *w_lo;
    cudaGetSymbolAddress((void**)&enc_hi, g_enc_hi);
    cudaGetSymbolAddress((void**)&enc_lo, g_enc_lo);
    cudaGetSymbolAddress((void**)&dec_hi, g_dec_hi);
    cudaGetSymbolAddress((void**)&dec_lo, g_dec_lo);
    cudaGetSymbolAddress((void**)&w_hi,   g_W_hi);
    cudaGetSymbolAddress((void**)&w_lo,   g_W_lo);

    // 1) fp32 -> bf16 hi/lo splits
    {
        int n4 = (SLEN * NB * HID) / 4;
        split_kernel<<<n4 / 256, 256>>>((const float4*)ctxt, (bf162*)enc_hi, (bf162*)enc_lo, n4);
        n4 = (TLEN * NB * HID) / 4;
        split_kernel<<<n4 / 256, 256>>>((const float4*)dec, (bf162*)dec_hi, (bf162*)dec_lo, n4);
        n4 = (HID * 2 * HID) / 4;
        split_kernel<<<n4 / 256, 256>>>((const float4*)W, (bf162*)w_hi, (bf162*)w_lo, n4);
    }

    // 2) scores -> attn region (raw)
    gemm1_scores<<<dim3(SLEN / 128, TLEN / 128, NB), 256, smem_nt>>>(attn);

    // 3) masked softmax in place + attn hi/lo split
    softmax_rows<<<NB * TLEN, 256>>>(attn, slen);

    // 4) ctx = attn @ enc
    gemm2_ctx<<<dim3(HID / 128, TLEN / 128, NB), 256, smem_tr>>>();

    // 5) states = tanh(concat(ctx,dec) @ W^T + b)
    gemm3_out<<<dim3(HID / 128, (TLEN * NB) / 128), 256, smem_nt>>>(bias, states);
}

// round 7
// speedup vs baseline: 3.1157x; 1.1509x over previous
#include <cuda_runtime.h>
#include <cuda_bf16.h>
#include <math.h>
#include <stdint.h>

#define SLEN 2048
#define TLEN 1024
#define NB   32
#define HID  1024
#define LDA  (NB * HID)

typedef __nv_bfloat16 bf16;
typedef __nv_bfloat162 bf162;

// ---------------------------------------------------------------------------
// Static scratch (no runtime allocation)
// ---------------------------------------------------------------------------
__device__ bf16 g_enc_hi [(size_t)SLEN * NB * HID];
__device__ bf16 g_enc_lo [(size_t)SLEN * NB * HID];
__device__ bf16 g_dec_hi [(size_t)TLEN * NB * HID];
__device__ bf16 g_dec_lo [(size_t)TLEN * NB * HID];
__device__ bf16 g_W_hi   [(size_t)HID * 2 * HID];
__device__ bf16 g_W_lo   [(size_t)HID * 2 * HID];
__device__ bf16 g_attn_hi[(size_t)NB * TLEN * SLEN];
__device__ bf16 g_attn_lo[(size_t)NB * TLEN * SLEN];
__device__ bf16 g_ctx_hi [(size_t)TLEN * NB * HID];   // [m=t*NB+b][h]
__device__ bf16 g_ctx_lo [(size_t)TLEN * NB * HID];

// ---------------------------------------------------------------------------
// Dtype-robust src_length read (int32[NB] or int64[NB]; word[1]==0 <=> int64)
// ---------------------------------------------------------------------------
__device__ __forceinline__ int read_len(const int* __restrict__ slen32, int b) {
    const bool is64 = (slen32[1] == 0);
    int len = is64 ? slen32[2 * b] : slen32[b];
    if (len < 1) len = 1;
    if (len > SLEN) len = SLEN;
    return len;
}

// ---------------------------------------------------------------------------
// fp32 -> (bf16 hi, bf16 lo) split
// ---------------------------------------------------------------------------
__global__ void split_kernel(const float4* __restrict__ x,
                             bf162* __restrict__ hi, bf162* __restrict__ lo, int n4)
{
    int i = blockIdx.x * blockDim.x + threadIdx.x;
    if (i >= n4) return;
    float4 v = x[i];
    bf16 h0 = __float2bfloat16(v.x), h1 = __float2bfloat16(v.y);
    bf16 h2 = __float2bfloat16(v.z), h3 = __float2bfloat16(v.w);
    hi[2 * i]     = __halves2bfloat162(h0, h1);
    hi[2 * i + 1] = __halves2bfloat162(h2, h3);
    lo[2 * i] = __halves2bfloat162(__float2bfloat16(v.x - __bfloat162float(h0)),
                                   __float2bfloat16(v.y - __bfloat162float(h1)));
    lo[2 * i + 1] = __halves2bfloat162(__float2bfloat16(v.z - __bfloat162float(h2)),
                                       __float2bfloat16(v.w - __bfloat162float(h3)));
}

// ---------------------------------------------------------------------------
// Primitives
// ---------------------------------------------------------------------------
__device__ __forceinline__ unsigned smem_u32(const void* p) {
    return (unsigned)__cvta_generic_to_shared(p);
}
__device__ __forceinline__ void cp16(unsigned dst, const void* src) {
    asm volatile("cp.async.cg.shared.global [%0], [%1], 16;" :: "r"(dst), "l"(src));
}
__device__ __forceinline__ void cp_commit() {
    asm volatile("cp.async.commit_group;" ::: "memory");
}
template <int N>
__device__ __forceinline__ void cp_wait() {
    asm volatile("cp.async.wait_group %0;" :: "n"(N) : "memory");
}

__device__ __forceinline__ void ldsm4(unsigned addr,
    unsigned& r0, unsigned& r1, unsigned& r2, unsigned& r3)
{
    asm volatile("ldmatrix.sync.aligned.m8n8.x4.shared.b16 {%0,%1,%2,%3}, [%4];"
        : "=r"(r0), "=r"(r1), "=r"(r2), "=r"(r3) : "r"(addr));
}
__device__ __forceinline__ void ldsm4t(unsigned addr,
    unsigned& r0, unsigned& r1, unsigned& r2, unsigned& r3)
{
    asm volatile("ldmatrix.sync.aligned.m8n8.x4.trans.shared.b16 {%0,%1,%2,%3}, [%4];"
        : "=r"(r0), "=r"(r1), "=r"(r2), "=r"(r3) : "r"(addr));
}
__device__ __forceinline__ void mma_bf16(float c[4],
    unsigned a0, unsigned a1, unsigned a2, unsigned a3, unsigned b0, unsigned b1)
{
    asm volatile(
        "mma.sync.aligned.m16n8k16.row.col.f32.bf16.bf16.f32 "
        "{%0,%1,%2,%3}, {%4,%5,%6,%7}, {%8,%9}, {%0,%1,%2,%3};"
        : "+f"(c[0]), "+f"(c[1]), "+f"(c[2]), "+f"(c[3])
        : "r"(a0), "r"(a1), "r"(a2), "r"(a3), "r"(b0), "r"(b1));
}

// Tile strides in elements (padded; row bytes are multiples of 16)
#define ASTR 40     // [row][32k]: 80B rows
#define BKSTR 136   // [32k][128n]: 272B rows

// Stage byte offsets
#define T_AH 0
#define T_AL 10240
#define T_BH 20480
#define T_BL 30720
#define STG_NT 40960
#define T2_BH 20480
#define T2_BL 29184
#define STG_TR 37888

// ---------------------------------------------------------------------------
// cp.async tile loaders
// ---------------------------------------------------------------------------
__device__ __forceinline__ void cpa_nt(unsigned sb, const bf16* __restrict__ g,
                                       size_t ld, int tid)
{
#pragma unroll
    for (int l = 0; l < 2; ++l) {
        int idx = tid + l * 256;
        int r = idx >> 2, q = idx & 3;
        cp16(sb + (unsigned)(r * ASTR + q * 8) * 2, g + (size_t)r * ld + q * 8);
    }
}
__device__ __forceinline__ void cpa_tr(unsigned sb, const bf16* __restrict__ g,
                                       size_t ld, int tid)
{
#pragma unroll
    for (int l = 0; l < 2; ++l) {
        int idx = tid + l * 256;
        int r = idx >> 4, q = idx & 15;
        cp16(sb + (unsigned)(r * BKSTR + q * 8) * 2, g + (size_t)r * ld + q * 8);
    }
}

// ---------------------------------------------------------------------------
// One 32-wide K chunk of 3-term split MMAs.
// ---------------------------------------------------------------------------
template <bool BT>
__device__ __forceinline__ void mma_chunk(
    const bf16* As_hi, const bf16* As_lo,
    const bf16* Bs_hi, const bf16* Bs_lo,
    float acc[4][4][4], int lane, int m_base, int n_base)
{
    const int ra = (lane & 7) + ((lane >> 3) & 1) * 8;
    const int ka = (lane >> 4) * 8;
    const int rb = (lane & 7) + (lane >> 4) * 8;
    const int kbo = ((lane >> 3) & 1) * 8;
    const int krt = (lane & 7) + ((lane >> 3) & 1) * 8;
    const int nft = (lane >> 4) * 8;

#pragma unroll
    for (int kk = 0; kk < 32; kk += 16) {
        unsigned ah[4][4], al[4][4], bh[2][4], bl[2][4];
#pragma unroll
        for (int i = 0; i < 4; ++i) {
            unsigned off = ((m_base + 16 * i + ra) * ASTR + kk + ka) * 2;
            ldsm4(smem_u32(As_hi) + off, ah[i][0], ah[i][1], ah[i][2], ah[i][3]);
            ldsm4(smem_u32(As_lo) + off, al[i][0], al[i][1], al[i][2], al[i][3]);
        }
#pragma unroll
        for (int jB = 0; jB < 2; ++jB) {
            if (!BT) {
                unsigned off = ((n_base + 16 * jB + rb) * ASTR + kk + kbo) * 2;
                ldsm4(smem_u32(Bs_hi) + off, bh[jB][0], bh[jB][1], bh[jB][2], bh[jB][3]);
                ldsm4(smem_u32(Bs_lo) + off, bl[jB][0], bl[jB][1], bl[jB][2], bl[jB][3]);
            } else {
                unsigned off = ((kk + krt) * BKSTR + n_base + 16 * jB + nft) * 2;
                ldsm4t(smem_u32(Bs_hi) + off, bh[jB][0], bh[jB][1], bh[jB][2], bh[jB][3]);
                ldsm4t(smem_u32(Bs_lo) + off, bl[jB][0], bl[jB][1], bl[jB][2], bl[jB][3]);
            }
        }
#pragma unroll
        for (int i = 0; i < 4; ++i)
#pragma unroll
            for (int j = 0; j < 4; ++j) {
                const int jB = j >> 1, s = (j & 1) * 2;
                mma_bf16(acc[i][j], ah[i][0], ah[i][1], ah[i][2], ah[i][3], bh[jB][s], bh[jB][s + 1]);
                mma_bf16(acc[i][j], ah[i][0], ah[i][1], ah[i][2], ah[i][3], bl[jB][s], bl[jB][s + 1]);
                mma_bf16(acc[i][j], al[i][0], al[i][1], al[i][2], al[i][3], bh[jB][s], bh[jB][s + 1]);
            }
    }
}

// ---------------------------------------------------------------------------
// GEMM1: scores = dec . enc. Blocks whose entire n-tile is masked exit early
// (softmax never reads masked score values).
// ---------------------------------------------------------------------------
__global__ __launch_bounds__(256, 2)
void gemm1_scores(float* __restrict__ scores, const int* __restrict__ slen32)
{
    extern __shared__ __align__(16) char dsm[];
    const int b = blockIdx.z, m0 = blockIdx.y * 128, n0 = blockIdx.x * 128;

    if (n0 >= read_len(slen32, b)) return;   // fully masked tile: skip

    const int tid = threadIdx.x, lane = tid & 31, wid = tid >> 5;
    const int m_base = (wid >> 2) * 64, n_base = (wid & 3) * 32;

    const unsigned sb = smem_u32(dsm);
    const unsigned st[2] = { sb, sb + STG_NT };

    const bf16* Ah = g_dec_hi + (size_t)m0 * LDA + (size_t)b * HID;
    const bf16* Al = g_dec_lo + (size_t)m0 * LDA + (size_t)b * HID;
    const bf16* Bh = g_enc_hi + (size_t)n0 * LDA + (size_t)b * HID;
    const bf16* Bl = g_enc_lo + (size_t)n0 * LDA + (size_t)b * HID;
    const int NC = HID / 32;  // 32

    cpa_nt(st[0] + T_AH, Ah, LDA, tid);
    cpa_nt(st[0] + T_AL, Al, LDA, tid);
    cpa_nt(st[0] + T_BH, Bh, LDA, tid);
    cpa_nt(st[0] + T_BL, Bl, LDA, tid);
    cp_commit();

    float acc[4][4][4] = {};
    for (int m = 0; m < NC; ++m) {
        const int s = m & 1;
        if (m + 1 < NC) {
            const int j = (m + 1) & 1;
            const size_t kb = (size_t)(m + 1) * 32;
            cpa_nt(st[j] + T_AH, Ah + kb, LDA, tid);
            cpa_nt(st[j] + T_AL, Al + kb, LDA, tid);
            cpa_nt(st[j] + T_BH, Bh + kb, LDA, tid);
            cpa_nt(st[j] + T_BL, Bl + kb, LDA, tid);
            cp_commit();
            cp_wait<1>();
        } else {
            cp_wait<0>();
        }
        __syncthreads();
        mma_chunk<false>((const bf16*)(dsm + (st[s] - sb) + T_AH),
                         (const bf16*)(dsm + (st[s] - sb) + T_AL),
                         (const bf16*)(dsm + (st[s] - sb) + T_BH),
                         (const bf16*)(dsm + (st[s] - sb) + T_BL),
                         acc, lane, m_base, n_base);
        __syncthreads();
    }

    float* C = scores + (size_t)b * TLEN * SLEN;
    const int r0 = lane >> 2, c0 = (lane & 3) * 2;
#pragma unroll
    for (int i = 0; i < 4; ++i)
#pragma unroll
        for (int j = 0; j < 4; ++j) {
            const int row = m0 + m_base + 16 * i + r0;
            const int col = n0 + n_base + 8 * j + c0;
            *reinterpret_cast<float2*>(C + (size_t)row * SLEN + col)
                = make_float2(acc[i][j][0], acc[i][j][1]);
            *reinterpret_cast<float2*>(C + (size_t)(row + 8) * SLEN + col)
                = make_float2(acc[i][j][2], acc[i][j][3]);
        }
}

// ---------------------------------------------------------------------------
// Masked softmax over S, in place; emits bf16 hi/lo split of attn.
// ---------------------------------------------------------------------------
__global__ __launch_bounds__(256)
void softmax_rows(float* __restrict__ scores, const int* __restrict__ slen32)
{
    __shared__ float red[256];
    __shared__ int s_len;

    const int row = blockIdx.x;
    const int b = row / TLEN;
    const int tid = threadIdx.x;

    if (tid == 0) s_len = read_len(slen32, b);
    __syncthreads();
    const int len = s_len;

    float* p = scores + (size_t)row * SLEN;
    float4 v0 = reinterpret_cast<const float4*>(p)[tid];
    float4 v1 = reinterpret_cast<const float4*>(p)[tid + 256];

    float e[8] = { v0.x, v0.y, v0.z, v0.w, v1.x, v1.y, v1.z, v1.w };
    int s[8];
#pragma unroll
    for (int q = 0; q < 4; ++q) { s[q] = tid * 4 + q; s[4 + q] = (tid + 256) * 4 + q; }

    float m = -1e30f;
#pragma unroll
    for (int q = 0; q < 8; ++q) if (s[q] < len) m = fmaxf(m, e[q]);
    red[tid] = m; __syncthreads();
    for (int off = 128; off > 0; off >>= 1) {
        if (tid < off) red[tid] = fmaxf(red[tid], red[tid + off]);
        __syncthreads();
    }
    const float rowmax = red[0];
    __syncthreads();

    float sum = 0.f;
#pragma unroll
    for (int q = 0; q < 8; ++q) {
        float ev = (s[q] < len) ? expf(e[q] - rowmax) : 0.f;
        e[q] = ev; sum += ev;
    }
    red[tid] = sum; __syncthreads();
    for (int off = 128; off > 0; off >>= 1) {
        if (tid < off) red[tid] += red[tid + off];
        __syncthreads();
    }
    const float inv = 1.f / red[0];

#pragma unroll
    for (int q = 0; q < 8; ++q) e[q] *= inv;

    reinterpret_cast<float4*>(p)[tid]       = make_float4(e[0], e[1], e[2], e[3]);
    reinterpret_cast<float4*>(p)[tid + 256] = make_float4(e[4], e[5], e[6], e[7]);

    bf162* phh = reinterpret_cast<bf162*>(g_attn_hi + (size_t)row * SLEN);
    bf162* pll = reinterpret_cast<bf162*>(g_attn_lo + (size_t)row * SLEN);
#pragma unroll
    for (int h = 0; h < 2; ++h) {
        const int base = (h == 0) ? tid * 2 : (tid + 256) * 2;
        const int qb = h * 4;
        bf16 h0 = __float2bfloat16(e[qb + 0]), h1 = __float2bfloat16(e[qb + 1]);
        bf16 h2 = __float2bfloat16(e[qb + 2]), h3 = __float2bfloat16(e[qb + 3]);
        phh[base]     = __halves2bfloat162(h0, h1);
        phh[base + 1] = __halves2bfloat162(h2, h3);
        pll[base] = __halves2bfloat162(
            __float2bfloat16(e[qb + 0] - __bfloat162float(h0)),
            __float2bfloat16(e[qb + 1] - __bfloat162float(h1)));
        pll[base + 1] = __halves2bfloat162(
            __float2bfloat16(e[qb + 2] - __bfloat162float(h2)),
            __float2bfloat16(e[qb + 3] - __bfloat162float(h3)));
    }
}

// ---------------------------------------------------------------------------
// GEMM2: ctx = attn . enc. K loop truncated at ceil(len/32): attn is exactly
// zero for s >= len, so skipped chunks contribute exactly nothing.
// ---------------------------------------------------------------------------
__global__ __launch_bounds__(256, 2)
void gemm2_ctx(const int* __restrict__ slen32)
{
    extern __shared__ __align__(16) char dsm[];
    const int b = blockIdx.z, m0 = blockIdx.y * 128, n0 = blockIdx.x * 128;
    const int tid = threadIdx.x, lane = tid & 31, wid = tid >> 5;
    const int m_base = (wid >> 2) * 64, n_base = (wid & 3) * 32;

    const unsigned sb = smem_u32(dsm);
    const unsigned st[2] = { sb, sb + STG_TR };

    const bf16* Ah = g_attn_hi + (size_t)b * TLEN * SLEN + (size_t)m0 * SLEN;
    const bf16* Al = g_attn_lo + (size_t)b * TLEN * SLEN + (size_t)m0 * SLEN;
    const bf16* Bh = g_enc_hi + (size_t)b * HID + n0;
    const bf16* Bl = g_enc_lo + (size_t)b * HID + n0;
    const int NC = (read_len(slen32, b) + 31) / 32;   // <= 64

    cpa_nt(st[0] + T_AH, Ah, SLEN, tid);
    cpa_nt(st[0] + T_AL, Al, SLEN, tid);
    cpa_tr(st[0] + T2_BH, Bh, LDA, tid);
    cpa_tr(st[0] + T2_BL, Bl, LDA, tid);
    cp_commit();

    float acc[4][4][4] = {};
    for (int m = 0; m < NC; ++m) {
        const int s = m & 1;
        if (m + 1 < NC) {
            const int j = (m + 1) & 1;
            const size_t kb = (size_t)(m + 1) * 32;
            cpa_nt(st[j] + T_AH, Ah + kb, SLEN, tid);
            cpa_nt(st[j] + T_AL, Al + kb, SLEN, tid);
            cpa_tr(st[j] + T2_BH, Bh + kb * LDA, LDA, tid);
            cpa_tr(st[j] + T2_BL, Bl + kb * LDA, LDA, tid);
            cp_commit();
            cp_wait<1>();
        } else {
            cp_wait<0>();
        }
        __syncthreads();
        mma_chunk<true>((const bf16*)(dsm + (st[s] - sb) + T_AH),
                        (const bf16*)(dsm + (st[s] - sb) + T_AL),
                        (const bf16*)(dsm + (st[s] - sb) + T2_BH),
                        (const bf16*)(dsm + (st[s] - sb) + T2_BL),
                        acc, lane, m_base, n_base);
        __syncthreads();
    }

    const int r0 = lane >> 2, c0 = (lane & 3) * 2;
#pragma unroll
    for (int i = 0; i < 4; ++i)
#pragma unroll
        for (int j = 0; j < 4; ++j) {
            const int mrow = m0 + m_base + 16 * i + r0;
            const int col = n0 + n_base + 8 * j + c0;
#pragma unroll
            for (int hh = 0; hh < 2; ++hh) {
                const size_t off = (size_t)b * HID + (size_t)(mrow + 8 * hh) * LDA + col;
                const float va = acc[i][j][2 * hh], vb = acc[i][j][2 * hh + 1];
                bf16 ha = __float2bfloat16(va), hb = __float2bfloat16(vb);
                *reinterpret_cast<bf162*>(g_ctx_hi + off) = __halves2bfloat162(ha, hb);
                *reinterpret_cast<bf162*>(g_ctx_lo + off) = __halves2bfloat162(
                    __float2bfloat16(va - __bfloat162float(ha)),
                    __float2bfloat16(vb - __bfloat162float(hb)));
            }
        }
}

// ---------------------------------------------------------------------------
// GEMM3: states = tanh(concat(ctx,dec) . W^T + bias)
// ---------------------------------------------------------------------------
__global__ __launch_bounds__(256, 2)
void gemm3_out(const float* __restrict__ bias, float* __restrict__ outp)
{
    extern __shared__ __align__(16) char dsm[];
    const int m0 = blockIdx.y * 128, n0 = blockIdx.x * 128;
    const int tid = threadIdx.x, lane = tid & 31, wid = tid >> 5;
    const int m_base = (wid >> 2) * 64, n_base = (wid & 3) * 32;

    const unsigned sb = smem_u32(dsm);
    const unsigned st[2] = { sb, sb + STG_NT };

    const bf16* CtxH = g_ctx_hi + (size_t)m0 * HID;
    const bf16* CtxL = g_ctx_lo + (size_t)m0 * HID;
    const bf16* DecH = g_dec_hi + (size_t)m0 * HID;
    const bf16* DecL = g_dec_lo + (size_t)m0 * HID;
    const bf16* Bh = g_W_hi + (size_t)n0 * (2 * HID);
    const bf16* Bl = g_W_lo + (size_t)n0 * (2 * HID);
    const int NC = (2 * HID) / 32;  // 64

    cpa_nt(st[0] + T_AH, CtxH, HID, tid);
    cpa_nt(st[0] + T_AL, CtxL, HID, tid);
    cpa_nt(st[0] + T_BH, Bh, 2 * HID, tid);
    cpa_nt(st[0] + T_BL, Bl, 2 * HID, tid);
    cp_commit();

    float acc[4][4][4] = {};
    for (int m = 0; m < NC; ++m) {
        const int s = m & 1;
        if (m + 1 < NC) {
            const int j = (m + 1) & 1;
            const int kb = (m + 1) * 32;
            const bf16* pah; const bf16* pal;
            if (kb < HID) { pah = CtxH + kb; pal = CtxL + kb; }
            else          { pah = DecH + (kb - HID); pal = DecL + (kb - HID); }
            cpa_nt(st[j] + T_AH, pah, HID, tid);
            cpa_nt(st[j] + T_AL, pal, HID, tid);
            cpa_nt(st[j] + T_BH, Bh + kb, 2 * HID, tid);
            cpa_nt(st[j] + T_BL, Bl + kb, 2 * HID, tid);
            cp_commit();
            cp_wait<1>();
        } else {
            cp_wait<0>();
        }
        __syncthreads();
        mma_chunk<false>((const bf16*)(dsm + (st[s] - sb) + T_AH),
                         (const bf16*)(dsm + (st[s] - sb) + T_AL),
                         (const bf16*)(dsm + (st[s] - sb) + T_BH),
                         (const bf16*)(dsm + (st[s] - sb) + T_BL),
                         acc, lane, m_base, n_base);
        __syncthreads();
    }

    const int r0 = lane >> 2, c0 = (lane & 3) * 2;
#pragma unroll
    for (int i = 0; i < 4; ++i)
#pragma unroll
        for (int j = 0; j < 4; ++j) {
            const int row = m0 + m_base + 16 * i + r0;
            const int col = n0 + n_base + 8 * j + c0;
            const float b0 = bias[col], b1 = bias[col + 1];
            *reinterpret_cast<float2*>(outp + (size_t)row * HID + col)
                = make_float2(tanhf(acc[i][j][0] + b0), tanhf(acc[i][j][1] + b1));
            *reinterpret_cast<float2*>(outp + (size_t)(row + 8) * HID + col)
                = make_float2(tanhf(acc[i][j][2] + b0), tanhf(acc[i][j][3] + b1));
        }
}

// ---------------------------------------------------------------------------
// kernel_launch — inputs identified by element count (order-proof)
// ---------------------------------------------------------------------------
extern "C" void kernel_launch(void* const* d_in, const int* in_sizes, int n_in,
                              void* d_out, int out_size)
{
    const float* ctxt = nullptr;
    const int*   slen = nullptr;
    const float* dec  = nullptr;
    const float* W    = nullptr;
    const float* bias = nullptr;

    for (int i = 0; i < n_in; ++i) {
        switch (in_sizes[i]) {
            case SLEN * NB * HID: ctxt = (const float*)d_in[i]; break;
            case TLEN * NB * HID: dec  = (const float*)d_in[i]; break;
            case HID * 2 * HID:   W    = (const float*)d_in[i]; break;
            case HID:             bias = (const float*)d_in[i]; break;
            case NB:              slen = (const int*)d_in[i];   break;
        }
    }

    float* outp   = (float*)d_out;
    float* states = outp;                              // [T,B,H]
    float* attn   = outp + (size_t)TLEN * NB * HID;    // [B,T,S]

    const int smem_nt = 2 * STG_NT;  // 81920
    const int smem_tr = 2 * STG_TR;  // 75776
    cudaFuncSetAttribute(gemm1_scores, cudaFuncAttributeMaxDynamicSharedMemorySize, smem_nt);
    cudaFuncSetAttribute(gemm2_ctx,    cudaFuncAttributeMaxDynamicSharedMemorySize, smem_tr);
    cudaFuncSetAttribute(gemm3_out,    cudaFuncAttributeMaxDynamicSharedMemorySize, smem_nt);

    bf16 *enc_hi, *enc_lo, *dec_hi, *dec_lo, *w_hi, *w_lo;
    cudaGetSymbolAddress((void**)&enc_hi, g_enc_hi);
    cudaGetSymbolAddress((void**)&enc_lo, g_enc_lo);
    cudaGetSymbolAddress((void**)&dec_hi, g_dec_hi);
    cudaGetSymbolAddress((void**)&dec_lo, g_dec_lo);
    cudaGetSymbolAddress((void**)&w_hi,   g_W_hi);
    cudaGetSymbolAddress((void**)&w_lo,   g_W_lo);

    // 1) fp32 -> bf16 hi/lo splits
    {
        int n4 = (SLEN * NB * HID) / 4;
        split_kernel<<<n4 / 256, 256>>>((const float4*)ctxt, (bf162*)enc_hi, (bf162*)enc_lo, n4);
        n4 = (TLEN * NB * HID) / 4;
        split_kernel<<<n4 / 256, 256>>>((const float4*)dec, (bf162*)dec_hi, (bf162*)dec_lo, n4);
        n4 = (HID * 2 * HID) / 4;
        split_kernel<<<n4 / 256, 256>>>((const float4*)W, (bf162*)w_hi, (bf162*)w_lo, n4);
    }

    // 2) scores -> attn region (masked n-tiles skipped)
    gemm1_scores<<<dim3(SLEN / 128, TLEN / 128, NB), 256, smem_nt>>>(attn, slen);

    // 3) masked softmax in place + attn hi/lo split
    softmax_rows<<<NB * TLEN, 256>>>(attn, slen);

    // 4) ctx = attn @ enc (K truncated at src_length per batch)
    gemm2_ctx<<<dim3(HID / 128, TLEN / 128, NB), 256, smem_tr>>>(slen);

    // 5) states = tanh(concat(ctx,dec) @ W^T + b)
    gemm3_out<<<dim3(HID / 128, (TLEN * NB) / 128), 256, smem_nt>>>(bias, states);
}